// round 8
// baseline (speedup 1.0000x reference)
#include <cuda_runtime.h>

#define Bv 16
#define Cv 512
#define Nv 9216
#define Kv 32
#define TN 512
#define NT (Nv / TN)     // 18 n-tiles for k_assign
#define CH 128           // k_agg chunk (n per stage)
#define NCH (Nv / CH)    // 72 chunks
#define XP 130           // x staging pitch (floats): 2-way LDS conflict, 8B-aligned rows

// scratch (no cudaMalloc allowed)
__device__ __align__(16) float g_aw[(size_t)Bv * Nv * Kv];   // 18.9 MB aw[b][n][k]
__device__ float g_sawp[Bv * NT * Kv];                       // per-tile partial sums of aw

typedef unsigned long long u64;

__device__ __forceinline__ u64 pack2(float lo, float hi) {
    u64 r; asm("mov.b64 %0,{%1,%2};" : "=l"(r) : "f"(lo), "f"(hi)); return r;
}
__device__ __forceinline__ void unpack2(u64 v, float& lo, float& hi) {
    asm("mov.b64 {%0,%1},%2;" : "=f"(lo), "=f"(hi) : "l"(v));
}
// packed fp32x2 FMA (FFMA2) — PTX-only, 2x FFMA throughput on sm_103a
__device__ __forceinline__ u64 ffma2(u64 a, u64 b, u64 c) {
    u64 d; asm("fma.rn.f32x2 %0,%1,%2,%3;" : "=l"(d) : "l"(a), "l"(b), "l"(c)); return d;
}
__device__ __forceinline__ unsigned smem_u32(const void* p) {
    unsigned r;
    asm("{ .reg .u64 t; cvta.to.shared.u64 t, %1; cvt.u32.u64 %0, t; }" : "=r"(r) : "l"(p));
    return r;
}
__device__ __forceinline__ void cp8(unsigned dst, const void* src) {
    asm volatile("cp.async.ca.shared.global [%0], [%1], 8;" :: "r"(dst), "l"(src));
}
__device__ __forceinline__ void cp16(unsigned dst, const void* src) {
    asm volatile("cp.async.ca.shared.global [%0], [%1], 16;" :: "r"(dst), "l"(src));
}
#define CP_COMMIT() asm volatile("cp.async.commit_group;" ::: "memory")
#define CP_WAIT(N)  asm volatile("cp.async.wait_group %0;" :: "n"(N) : "memory")

// ---------------------------------------------------------------------------
// Kernel 1: per (b, 512-n tile): logits via scaled L2, softmax over K=32,
// write aw, write deterministic per-tile sum_aw partials.
// Thread owns n = n0+2t, n0+2t+1; k-pairs packed f32x2; depth-4 LDG pipeline.
// ---------------------------------------------------------------------------
__global__ void __launch_bounds__(256, 2) k_assign(
    const float* __restrict__ x, const float* __restrict__ cw,
    const float* __restrict__ scale)
{
    extern __shared__ float cwT[];                 // [Cv][Kv] = 64 KB, reused for reduction
    __shared__ float s_scale[Kv], s_sc2[Kv];
    const int tid = threadIdx.x;
    const int b   = blockIdx.y;
    const int n0  = blockIdx.x * TN;

    // transpose codewords into smem (gather loads hit L2 after wave 1; stores conflict-free)
    for (int i = tid; i < Cv * Kv; i += 256) {
        int k = i & 31, c = i >> 5;
        cwT[c * Kv + k] = cw[k * Cv + c];
    }
    __syncthreads();
    if (tid < Kv) {
        float s2 = 0.0f;
        #pragma unroll 8
        for (int c = 0; c < Cv; c++) { float v = cwT[c * Kv + tid]; s2 = fmaf(v, v, s2); }
        float sk = scale[tid];
        s_scale[tid] = sk;
        s_sc2[tid]   = sk * s2;
    }
    __syncthreads();

    const float* xb = x + (size_t)b * Cv * Nv + n0 + 2 * tid;

    u64 acc0[16], acc1[16];
    #pragma unroll
    for (int p = 0; p < 16; p++) { acc0[p] = 0ull; acc1[p] = 0ull; }
    u64 x2p = 0ull;

    // depth-4 software pipeline over C: 4 independent LDG.64 always in flight
    float2 buf[4];
    #pragma unroll
    for (int i = 0; i < 4; i++) buf[i] = *reinterpret_cast<const float2*>(xb + (size_t)i * Nv);

    for (int c0 = 0; c0 < Cv; c0 += 4) {
        float2 cur[4];
        #pragma unroll
        for (int i = 0; i < 4; i++) cur[i] = buf[i];
        #pragma unroll
        for (int i = 0; i < 4; i++) {
            int cn = c0 + 4 + i; cn = (cn < Cv) ? cn : 0;   // tail prefetch clamped (harmless)
            buf[i] = *reinterpret_cast<const float2*>(xb + (size_t)cn * Nv);
        }
        #pragma unroll
        for (int i = 0; i < 4; i++) {
            u64 xp = pack2(cur[i].x, cur[i].y);
            x2p = ffma2(xp, xp, x2p);
            u64 d0 = pack2(cur[i].x, cur[i].x);
            u64 d1 = pack2(cur[i].y, cur[i].y);
            const ulonglong2* row = reinterpret_cast<const ulonglong2*>(cwT + (c0 + i) * Kv);
            #pragma unroll
            for (int q = 0; q < 8; q++) {
                ulonglong2 w = row[q];             // broadcast LDS.128
                acc0[2 * q]     = ffma2(d0, w.x, acc0[2 * q]);
                acc1[2 * q]     = ffma2(d1, w.x, acc1[2 * q]);
                acc0[2 * q + 1] = ffma2(d0, w.y, acc0[2 * q + 1]);
                acc1[2 * q + 1] = ffma2(d1, w.y, acc1[2 * q + 1]);
            }
        }
    }

    float xcA[Kv], xcB[Kv], x2A, x2B;
    #pragma unroll
    for (int p = 0; p < 16; p++) {
        unpack2(acc0[p], xcA[2 * p], xcA[2 * p + 1]);
        unpack2(acc1[p], xcB[2 * p], xcB[2 * p + 1]);
    }
    unpack2(x2p, x2A, x2B);

    float* awout = g_aw + ((size_t)b * Nv + n0 + 2 * tid) * Kv;

    // in-place softmax for n (even)
    {
        float m = -1e30f;
        #pragma unroll
        for (int k = 0; k < Kv; k++) {
            float v = fmaf(s_scale[k], x2A - 2.0f * xcA[k], s_sc2[k]);
            xcA[k] = v; m = fmaxf(m, v);
        }
        float s = 0.0f;
        #pragma unroll
        for (int k = 0; k < Kv; k++) { float e = __expf(xcA[k] - m); xcA[k] = e; s += e; }
        float r = 1.0f / s;
        #pragma unroll
        for (int k = 0; k < Kv; k++) xcA[k] *= r;
        #pragma unroll
        for (int q = 0; q < 8; q++)
            reinterpret_cast<float4*>(awout)[q] =
                make_float4(xcA[4 * q], xcA[4 * q + 1], xcA[4 * q + 2], xcA[4 * q + 3]);
    }
    // in-place softmax for n+1 (odd)
    {
        float m = -1e30f;
        #pragma unroll
        for (int k = 0; k < Kv; k++) {
            float v = fmaf(s_scale[k], x2B - 2.0f * xcB[k], s_sc2[k]);
            xcB[k] = v; m = fmaxf(m, v);
        }
        float s = 0.0f;
        #pragma unroll
        for (int k = 0; k < Kv; k++) { float e = __expf(xcB[k] - m); xcB[k] = e; s += e; }
        float r = 1.0f / s;
        #pragma unroll
        for (int k = 0; k < Kv; k++) xcB[k] *= r;
        #pragma unroll
        for (int q = 0; q < 8; q++)
            reinterpret_cast<float4*>(awout + Kv)[q] =
                make_float4(xcB[4 * q], xcB[4 * q + 1], xcB[4 * q + 2], xcB[4 * q + 3]);
    }

    // deterministic block-level sum_aw: transpose through smem (reuses cwT), fixed order
    __syncthreads();                               // all warps done reading cwT
    float* red = cwT;                              // [256][33] = 33.8 KB
    #pragma unroll
    for (int k = 0; k < Kv; k++) red[tid * 33 + k] = xcA[k] + xcB[k];
    __syncthreads();
    if (tid < Kv) {
        float s = 0.0f;
        #pragma unroll 8
        for (int t = 0; t < 256; t++) s += red[t * 33 + tid];
        g_sawp[(b * NT + blockIdx.x) * Kv + tid] = s;
    }
}

// ---------------------------------------------------------------------------
// Kernel 2: enc[b][k][c] = sum_n aw[n][k]*x[c][n] - sum_aw[b][k]*cw[k][c]
// Block = (b, 32 c's). cp.async double-buffered block-wide staging of
// (32c x 128n) x-tile + (128n x 32k) aw-tile. 8 warps split the 128 n's.
// ---------------------------------------------------------------------------
__global__ void __launch_bounds__(256, 2) k_agg(
    const float* __restrict__ x, const float* __restrict__ cw,
    float* __restrict__ out)
{
    extern __shared__ float sm[];
    float* xs  = sm;                     // [2][32][XP]  = 33280 B
    float* aws = sm + 2 * 32 * XP;       // [2][CH][32]  = 32768 B
    const unsigned xs_u  = smem_u32(xs);
    const unsigned aws_u = smem_u32(aws);

    const int tid = threadIdx.x, w = tid >> 5, l = tid & 31;
    const int b  = blockIdx.y;
    const int cb = blockIdx.x * 32;
    const float* xb  = x + ((size_t)b * Cv + cb) * Nv;
    const float* awb = g_aw + (size_t)b * Nv * Kv;

    u64 acc[16];
    #pragma unroll
    for (int p = 0; p < 16; p++) acc[p] = 0ull;

    // precompute per-thread staging descriptors
    // x: 8 x 8B copies/thread; aw: 4 x 16B copies/thread
    // ---- stage chunk 0 into buffer 0 ----
    {
        #pragma unroll
        for (int r = 0; r < 8; r++) {
            int i = tid + 256 * r; int c = i >> 6; int m = i & 63;
            cp8(xs_u + (unsigned)(c * XP + m * 2) * 4, xb + (size_t)c * Nv + m * 2);
        }
        #pragma unroll
        for (int r = 0; r < 4; r++) {
            int i = tid + 256 * r; int n = i >> 3; int k4 = i & 7;
            cp16(aws_u + (unsigned)(n * 32 + k4 * 4) * 4, awb + (size_t)n * Kv + k4 * 4);
        }
        CP_COMMIT();
    }

    for (int t = 0; t < NCH - 1; t++) {
        // stage chunk t+1 into buffer (t+1)&1
        {
            const int s = (t + 1) & 1;
            const int n0 = (t + 1) * CH;
            #pragma unroll
            for (int r = 0; r < 8; r++) {
                int i = tid + 256 * r; int c = i >> 6; int m = i & 63;
                cp8(xs_u + (unsigned)(s * 32 * XP + c * XP + m * 2) * 4,
                    xb + (size_t)c * Nv + n0 + m * 2);
            }
            #pragma unroll
            for (int r = 0; r < 4; r++) {
                int i = tid + 256 * r; int n = i >> 3; int k4 = i & 7;
                cp16(aws_u + (unsigned)(s * CH * 32 + n * 32 + k4 * 4) * 4,
                     awb + (size_t)(n0 + n) * Kv + k4 * 4);
            }
            CP_COMMIT();
        }
        CP_WAIT(1);                      // chunk t complete (t+1 still in flight)
        __syncthreads();
        // compute chunk t from buffer t&1; warp w handles n = w*16..w*16+15
        {
            const int s = t & 1;
            const float* xr = xs + s * 32 * XP + l * XP + w * 16;
            const float* ar = aws + s * CH * 32 + (w * 16) * 32;
            #pragma unroll
            for (int j = 0; j < 16; j++) {
                float xv = xr[j];                          // 2-way-conflict LDS
                u64 xp = pack2(xv, xv);
                const ulonglong2* row = reinterpret_cast<const ulonglong2*>(ar + j * 32);
                #pragma unroll
                for (int q = 0; q < 8; q++) {
                    ulonglong2 a2 = row[q];                // broadcast LDS.128
                    acc[2 * q]     = ffma2(xp, a2.x, acc[2 * q]);
                    acc[2 * q + 1] = ffma2(xp, a2.y, acc[2 * q + 1]);
                }
            }
        }
        __syncthreads();                 // buffer t&1 free before overwrite at t+2's stage
    }
    // last chunk
    CP_WAIT(0);
    __syncthreads();
    {
        const int s = (NCH - 1) & 1;
        const float* xr = xs + s * 32 * XP + l * XP + w * 16;
        const float* ar = aws + s * CH * 32 + (w * 16) * 32;
        #pragma unroll
        for (int j = 0; j < 16; j++) {
            float xv = xr[j];
            u64 xp = pack2(xv, xv);
            const ulonglong2* row = reinterpret_cast<const ulonglong2*>(ar + j * 32);
            #pragma unroll
            for (int q = 0; q < 8; q++) {
                ulonglong2 a2 = row[q];
                acc[2 * q]     = ffma2(xp, a2.x, acc[2 * q]);
                acc[2 * q + 1] = ffma2(xp, a2.y, acc[2 * q + 1]);
            }
        }
    }

    // cross-warp reduction + fused epilogue (reuses xs region: 32 KB < 33280 B)
    __syncthreads();
    u64* red = reinterpret_cast<u64*>(sm);
    #pragma unroll
    for (int p = 0; p < 16; p++) red[(w * 16 + p) * 32 + l] = acc[p];
    __syncthreads();

    #pragma unroll
    for (int pp = 0; pp < 2; pp++) {
        int p = 2 * w + pp;
        float v0 = 0.0f, v1 = 0.0f;
        #pragma unroll
        for (int ww = 0; ww < 8; ww++) {
            float a, bb; unpack2(red[(ww * 16 + p) * 32 + l], a, bb);
            v0 += a; v1 += bb;
        }
        int k0 = 2 * p;
        int c  = cb + l;
        float s0 = 0.0f, s1 = 0.0f;
        #pragma unroll
        for (int t = 0; t < NT; t++) {
            s0 += g_sawp[(b * NT + t) * Kv + k0];
            s1 += g_sawp[(b * NT + t) * Kv + k0 + 1];
        }
        out[((size_t)b * Kv + k0) * Cv + c]     = v0 - s0 * cw[k0 * Cv + c];
        out[((size_t)b * Kv + k0 + 1) * Cv + c] = v1 - s1 * cw[(k0 + 1) * Cv + c];
    }
}

extern "C" void kernel_launch(void* const* d_in, const int* in_sizes, int n_in,
                              void* d_out, int out_size)
{
    const float* x  = (const float*)d_in[0];   // (B, C, H, W)
    const float* cw = (const float*)d_in[1];   // (K, C)
    const float* sc = (const float*)d_in[2];   // (K,)
    float* out = (float*)d_out;                // (B, K, C)

    static int inited = 0;
    if (!inited) {
        cudaFuncSetAttribute(k_assign, cudaFuncAttributeMaxDynamicSharedMemorySize, Cv * Kv * 4);
        cudaFuncSetAttribute(k_agg, cudaFuncAttributeMaxDynamicSharedMemorySize,
                             (2 * 32 * XP + 2 * CH * 32) * 4);
        inited = 1;
    }

    k_assign<<<dim3(NT, Bv), 256, Cv * Kv * 4>>>(x, cw, sc);
    k_agg<<<dim3(Cv / 32, Bv), 256, (2 * 32 * XP + 2 * CH * 32) * 4>>>(x, cw, out);
}

// round 9
// speedup vs baseline: 1.0631x; 1.0631x over previous
#include <cuda_runtime.h>

#define Bv 16
#define Cv 512
#define Nv 9216
#define Kv 32
#define TN 512
#define NT (Nv / TN)     // 18 n-tiles for k_assign
#define CH 128           // k_agg chunk (n per stage)
#define NCH (Nv / CH)    // 72 chunks
#define CB 64            // k_agg c's per block

// scratch (no cudaMalloc allowed)
__device__ __align__(16) float g_aw[(size_t)Bv * Nv * Kv];   // 18.9 MB aw[b][n][k]
__device__ float g_sawp[Bv * NT * Kv];                       // per-tile partial sums of aw

typedef unsigned long long u64;

__device__ __forceinline__ u64 pack2(float lo, float hi) {
    u64 r; asm("mov.b64 %0,{%1,%2};" : "=l"(r) : "f"(lo), "f"(hi)); return r;
}
__device__ __forceinline__ void unpack2(u64 v, float& lo, float& hi) {
    asm("mov.b64 {%0,%1},%2;" : "=f"(lo), "=f"(hi) : "l"(v));
}
// packed fp32x2 FMA (FFMA2) — PTX-only, 2x FFMA throughput on sm_103a
__device__ __forceinline__ u64 ffma2(u64 a, u64 b, u64 c) {
    u64 d; asm("fma.rn.f32x2 %0,%1,%2,%3;" : "=l"(d) : "l"(a), "l"(b), "l"(c)); return d;
}
__device__ __forceinline__ unsigned smem_u32(const void* p) {
    unsigned r;
    asm("{ .reg .u64 t; cvta.to.shared.u64 t, %1; cvt.u32.u64 %0, t; }" : "=r"(r) : "l"(p));
    return r;
}
__device__ __forceinline__ void cp4(unsigned dst, const void* src) {
    asm volatile("cp.async.ca.shared.global [%0], [%1], 4;" :: "r"(dst), "l"(src));
}
__device__ __forceinline__ void cp16(unsigned dst, const void* src) {
    asm volatile("cp.async.ca.shared.global [%0], [%1], 16;" :: "r"(dst), "l"(src));
}
#define CP_COMMIT() asm volatile("cp.async.commit_group;" ::: "memory")
#define CP_WAIT(N)  asm volatile("cp.async.wait_group %0;" :: "n"(N) : "memory")

// ---------------------------------------------------------------------------
// Kernel 1: per (b, 512-n tile): logits via scaled L2, softmax over K=32,
// write aw, write deterministic per-tile sum_aw partials.
// Thread owns n = n0+2t, n0+2t+1; k-pairs packed f32x2; depth-8 LDG pipeline.
// ---------------------------------------------------------------------------
__global__ void __launch_bounds__(256, 2) k_assign(
    const float* __restrict__ x, const float* __restrict__ cw,
    const float* __restrict__ scale)
{
    extern __shared__ float cwT[];                 // [Cv][Kv] = 64 KB, reused for reduction
    __shared__ float s_scale[Kv], s_sc2[Kv];
    const int tid = threadIdx.x;
    const int b   = blockIdx.y;
    const int n0  = blockIdx.x * TN;

    // transpose codewords into smem
    for (int i = tid; i < Cv * Kv; i += 256) {
        int k = i & 31, c = i >> 5;
        cwT[c * Kv + k] = cw[k * Cv + c];
    }
    __syncthreads();
    if (tid < Kv) {
        float s2 = 0.0f;
        #pragma unroll 8
        for (int c = 0; c < Cv; c++) { float v = cwT[c * Kv + tid]; s2 = fmaf(v, v, s2); }
        float sk = scale[tid];
        s_scale[tid] = sk;
        s_sc2[tid]   = sk * s2;
    }
    __syncthreads();

    const float* xb = x + (size_t)b * Cv * Nv + n0 + 2 * tid;

    u64 acc0[16], acc1[16];
    #pragma unroll
    for (int p = 0; p < 16; p++) { acc0[p] = 0ull; acc1[p] = 0ull; }
    u64 x2p = 0ull;

    // depth-8 LDG pipeline over C (consume-then-reload, no copy regs)
    float2 buf[8];
    #pragma unroll
    for (int i = 0; i < 8; i++) buf[i] = *reinterpret_cast<const float2*>(xb + (size_t)i * Nv);

    for (int c0 = 0; c0 < Cv; c0 += 8) {
        #pragma unroll
        for (int i = 0; i < 8; i++) {
            float2 xv = buf[i];
            int cn = c0 + 8 + i; cn = (cn < Cv) ? cn : 0;   // tail prefetch clamped (harmless)
            buf[i] = *reinterpret_cast<const float2*>(xb + (size_t)cn * Nv);

            u64 xp = pack2(xv.x, xv.y);
            x2p = ffma2(xp, xp, x2p);
            u64 d0 = pack2(xv.x, xv.x);
            u64 d1 = pack2(xv.y, xv.y);
            const ulonglong2* row = reinterpret_cast<const ulonglong2*>(cwT + (c0 + i) * Kv);
            #pragma unroll
            for (int q = 0; q < 8; q++) {
                ulonglong2 w = row[q];             // broadcast LDS.128
                acc0[2 * q]     = ffma2(d0, w.x, acc0[2 * q]);
                acc1[2 * q]     = ffma2(d1, w.x, acc1[2 * q]);
                acc0[2 * q + 1] = ffma2(d0, w.y, acc0[2 * q + 1]);
                acc1[2 * q + 1] = ffma2(d1, w.y, acc1[2 * q + 1]);
            }
        }
    }

    float xcA[Kv], xcB[Kv], x2A, x2B;
    #pragma unroll
    for (int p = 0; p < 16; p++) {
        unpack2(acc0[p], xcA[2 * p], xcA[2 * p + 1]);
        unpack2(acc1[p], xcB[2 * p], xcB[2 * p + 1]);
    }
    unpack2(x2p, x2A, x2B);

    float* awout = g_aw + ((size_t)b * Nv + n0 + 2 * tid) * Kv;

    // in-place softmax for n (even)
    {
        float m = -1e30f;
        #pragma unroll
        for (int k = 0; k < Kv; k++) {
            float v = fmaf(s_scale[k], x2A - 2.0f * xcA[k], s_sc2[k]);
            xcA[k] = v; m = fmaxf(m, v);
        }
        float s = 0.0f;
        #pragma unroll
        for (int k = 0; k < Kv; k++) { float e = __expf(xcA[k] - m); xcA[k] = e; s += e; }
        float r = 1.0f / s;
        #pragma unroll
        for (int k = 0; k < Kv; k++) xcA[k] *= r;
        #pragma unroll
        for (int q = 0; q < 8; q++)
            reinterpret_cast<float4*>(awout)[q] =
                make_float4(xcA[4 * q], xcA[4 * q + 1], xcA[4 * q + 2], xcA[4 * q + 3]);
    }
    // in-place softmax for n+1 (odd)
    {
        float m = -1e30f;
        #pragma unroll
        for (int k = 0; k < Kv; k++) {
            float v = fmaf(s_scale[k], x2B - 2.0f * xcB[k], s_sc2[k]);
            xcB[k] = v; m = fmaxf(m, v);
        }
        float s = 0.0f;
        #pragma unroll
        for (int k = 0; k < Kv; k++) { float e = __expf(xcB[k] - m); xcB[k] = e; s += e; }
        float r = 1.0f / s;
        #pragma unroll
        for (int k = 0; k < Kv; k++) xcB[k] *= r;
        #pragma unroll
        for (int q = 0; q < 8; q++)
            reinterpret_cast<float4*>(awout + Kv)[q] =
                make_float4(xcB[4 * q], xcB[4 * q + 1], xcB[4 * q + 2], xcB[4 * q + 3]);
    }

    // deterministic block-level sum_aw: transpose through smem (reuses cwT)
    __syncthreads();
    float* red = cwT;                              // [256][33]
    #pragma unroll
    for (int k = 0; k < Kv; k++) red[tid * 33 + k] = xcA[k] + xcB[k];
    __syncthreads();
    if (tid < Kv) {
        float s = 0.0f;
        #pragma unroll 8
        for (int t = 0; t < 256; t++) s += red[t * 33 + tid];
        g_sawp[(b * NT + blockIdx.x) * Kv + tid] = s;
    }
}

// ---------------------------------------------------------------------------
// Kernel 2: enc[b][k][c] = sum_n aw[n][k]*x[c][n] - sum_aw[b][k]*cw[k][c]
// Block = (b, 64 c's): lane owns c=cb+l and c=cb+32+l (32 f32x2 accumulators).
// cp.async double-buffered staging: x tile 64x128 (4B XOR swizzle,
// conflict-free reads) + aw tile 128x32. 8 warps split the 128 n's.
// Grid = 8 x 16 = 128 blocks: single wave.
// ---------------------------------------------------------------------------
__global__ void __launch_bounds__(256, 1) k_agg(
    const float* __restrict__ x, const float* __restrict__ cw,
    float* __restrict__ out)
{
    extern __shared__ float sm[];
    float* xs  = sm;                     // [2][64][128] = 64 KB, XOR-swizzled rows
    float* aws = sm + 2 * CB * CH;       // [2][128][32] = 32 KB
    __shared__ float s_sum[Kv];
    const unsigned xs_u  = smem_u32(xs);
    const unsigned aws_u = smem_u32(aws);

    const int tid = threadIdx.x, w = tid >> 5, l = tid & 31;
    const int b  = blockIdx.y;
    const int cb = blockIdx.x * CB;
    const float* xb  = x + ((size_t)b * Cv + cb) * Nv;
    const float* awb = g_aw + (size_t)b * Nv * Kv;

    u64 acc0[16], acc1[16];
    #pragma unroll
    for (int p = 0; p < 16; p++) { acc0[p] = 0ull; acc1[p] = 0ull; }

    const int c0t = tid >> 7;            // 0 or 1
    const int m   = tid & 127;           // fixed n-offset this thread stages

    // ---- stage chunk 0 into buffer 0 ----
    {
        #pragma unroll
        for (int r = 0; r < 32; r++) {
            int c  = c0t + 2 * r;
            int sw = m ^ (c & 31);
            cp4(xs_u + (unsigned)(c * CH + sw) * 4, xb + (size_t)c * Nv + m);
        }
        #pragma unroll
        for (int r = 0; r < 4; r++) {
            int i = tid + 256 * r; int n = i >> 3; int k4 = i & 7;
            cp16(aws_u + (unsigned)(n * 32 + k4 * 4) * 4, awb + (size_t)n * Kv + k4 * 4);
        }
        CP_COMMIT();
    }

    for (int t = 0; t < NCH - 1; t++) {
        // stage chunk t+1 into buffer (t+1)&1
        {
            const int s  = (t + 1) & 1;
            const int n0 = (t + 1) * CH;
            #pragma unroll
            for (int r = 0; r < 32; r++) {
                int c  = c0t + 2 * r;
                int sw = m ^ (c & 31);
                cp4(xs_u + (unsigned)(s * CB * CH + c * CH + sw) * 4,
                    xb + (size_t)c * Nv + n0 + m);
            }
            #pragma unroll
            for (int r = 0; r < 4; r++) {
                int i = tid + 256 * r; int n = i >> 3; int k4 = i & 7;
                cp16(aws_u + (unsigned)(s * CH * 32 + n * 32 + k4 * 4) * 4,
                     awb + (size_t)(n0 + n) * Kv + k4 * 4);
            }
            CP_COMMIT();
        }
        CP_WAIT(1);                      // chunk t complete (t+1 still in flight)
        __syncthreads();
        // compute chunk t from buffer t&1; warp w handles n = w*16..w*16+15
        {
            const int s = t & 1;
            const float* xr0 = xs + s * CB * CH + l * CH;          // c = cb + l
            const float* xr1 = xs + s * CB * CH + (l + 32) * CH;   // c = cb + 32 + l
            const float* ar  = aws + s * CH * 32 + (w * 16) * 32;
            #pragma unroll 4
            for (int j = 0; j < 16; j++) {
                int e = (w * 16 + j) ^ l;                 // swizzled, conflict-free
                float xv0 = xr0[e];
                float xv1 = xr1[e];
                u64 xp0 = pack2(xv0, xv0);
                u64 xp1 = pack2(xv1, xv1);
                const ulonglong2* row = reinterpret_cast<const ulonglong2*>(ar + j * 32);
                #pragma unroll
                for (int q = 0; q < 8; q++) {
                    ulonglong2 a2 = row[q];               // broadcast LDS.128
                    acc0[2 * q]     = ffma2(xp0, a2.x, acc0[2 * q]);
                    acc0[2 * q + 1] = ffma2(xp0, a2.y, acc0[2 * q + 1]);
                    acc1[2 * q]     = ffma2(xp1, a2.x, acc1[2 * q]);
                    acc1[2 * q + 1] = ffma2(xp1, a2.y, acc1[2 * q + 1]);
                }
            }
        }
        __syncthreads();                 // buffer t&1 free before overwrite at t+2's stage
    }
    // last chunk
    CP_WAIT(0);
    __syncthreads();
    {
        const int s = (NCH - 1) & 1;
        const float* xr0 = xs + s * CB * CH + l * CH;
        const float* xr1 = xs + s * CB * CH + (l + 32) * CH;
        const float* ar  = aws + s * CH * 32 + (w * 16) * 32;
        #pragma unroll 4
        for (int j = 0; j < 16; j++) {
            int e = (w * 16 + j) ^ l;
            float xv0 = xr0[e];
            float xv1 = xr1[e];
            u64 xp0 = pack2(xv0, xv0);
            u64 xp1 = pack2(xv1, xv1);
            const ulonglong2* row = reinterpret_cast<const ulonglong2*>(ar + j * 32);
            #pragma unroll
            for (int q = 0; q < 8; q++) {
                ulonglong2 a2 = row[q];
                acc0[2 * q]     = ffma2(xp0, a2.x, acc0[2 * q]);
                acc0[2 * q + 1] = ffma2(xp0, a2.y, acc0[2 * q + 1]);
                acc1[2 * q]     = ffma2(xp1, a2.x, acc1[2 * q]);
                acc1[2 * q + 1] = ffma2(xp1, a2.y, acc1[2 * q + 1]);
            }
        }
    }

    // cross-warp reduction + fused epilogue (reuses xs region: 64 KB exactly)
    __syncthreads();
    u64* red = reinterpret_cast<u64*>(sm);         // [w][p 0..31][l] u64
    #pragma unroll
    for (int p = 0; p < 16; p++) {
        red[(w * 32 + p)      * 32 + l] = acc0[p];
        red[(w * 32 + 16 + p) * 32 + l] = acc1[p];
    }
    if (tid < Kv) {                                // pre-reduce sum_aw once
        float s = 0.0f;
        #pragma unroll
        for (int t = 0; t < NT; t++) s += g_sawp[(b * NT + t) * Kv + tid];
        s_sum[tid] = s;
    }
    __syncthreads();

    #pragma unroll
    for (int i = 0; i < 4; i++) {
        int idx = tid + 256 * i;                   // 0..1023 -> (p, lane) columns
        int p = idx >> 5, ll = idx & 31;
        float v0 = 0.0f, v1 = 0.0f;
        #pragma unroll
        for (int ww = 0; ww < 8; ww++) {
            float a, bb; unpack2(red[(ww * 32 + p) * 32 + ll], a, bb);
            v0 += a; v1 += bb;
        }
        int half = p >> 4, pk = p & 15, k0 = 2 * pk;
        int c = cb + half * 32 + ll;
        float s0 = s_sum[k0], s1 = s_sum[k0 + 1];
        out[((size_t)b * Kv + k0)     * Cv + c] = v0 - s0 * cw[k0 * Cv + c];
        out[((size_t)b * Kv + k0 + 1) * Cv + c] = v1 - s1 * cw[(k0 + 1) * Cv + c];
    }
}

extern "C" void kernel_launch(void* const* d_in, const int* in_sizes, int n_in,
                              void* d_out, int out_size)
{
    const float* x  = (const float*)d_in[0];   // (B, C, H, W)
    const float* cw = (const float*)d_in[1];   // (K, C)
    const float* sc = (const float*)d_in[2];   // (K,)
    float* out = (float*)d_out;                // (B, K, C)

    static int inited = 0;
    if (!inited) {
        cudaFuncSetAttribute(k_assign, cudaFuncAttributeMaxDynamicSharedMemorySize, Cv * Kv * 4);
        cudaFuncSetAttribute(k_agg, cudaFuncAttributeMaxDynamicSharedMemorySize,
                             (2 * CB * CH + 2 * CH * 32) * 4);
        inited = 1;
    }

    k_assign<<<dim3(NT, Bv), 256, Cv * Kv * 4>>>(x, cw, sc);
    k_agg<<<dim3(Cv / CB, Bv), 256, (2 * CB * CH + 2 * CH * 32) * 4>>>(x, cw, out);
}